// round 2
// baseline (speedup 1.0000x reference)
#include <cuda_runtime.h>
#include <cuda_bf16.h>

// Problem constants (fixed by dataset): B=16, C=80, D=1024, S=14 (P=196)
#define BB 16
#define CC 80
#define DD 1024
#define PP 196
#define PT 8            // pixels per block in phase 1
#define SSTRIDE 1032    // padded smem stride (conflict-free both ways)

// Scratch (no allocation allowed -> device globals)
__device__ float g_imgT[BB * PP * DD];        // [b][p][d]  transposed img, 12.8MB
__device__ float g_scores[BB * CC * PP];      // [b][c][p]
__device__ float g_coef[BB * PP * CC];        // [b][p][c]

typedef unsigned long long ull;

__device__ __forceinline__ float tanh_fast(float x) {
    float y; asm("tanh.approx.f32 %0, %1;" : "=f"(y) : "f"(x)); return y;
}
__device__ __forceinline__ ull pack2(float a, float b) {
    ull r; asm("mov.b64 %0, {%1, %2};" : "=l"(r) : "f"(a), "f"(b)); return r;
}
__device__ __forceinline__ ull fma2(ull a, ull b, ull c) {
    ull d; asm("fma.rn.f32x2 %0, %1, %2, %3;" : "=l"(d) : "l"(a), "l"(b), "l"(c)); return d;
}
__device__ __forceinline__ float2 unpack2(ull a) {
    float lo, hi; asm("mov.b64 {%0, %1}, %2;" : "=f"(lo), "=f"(hi) : "l"(a));
    return make_float2(lo, hi);
}

// ---------------------------------------------------------------------------
// Phase 1: scores[b,c,p] = sum_d tanh(img[b,d,p]*word[c,d]) * w[d]
// Also writes imgT[b,p,d] (coalesced) for phase 3.
// grid (25, 16), block 256. Warp = pixel, lane owns d = 4*(lane+32k)+0..3.
// img slice and w cached in registers across all 80 classes (MUFU-bound loop).
// ---------------------------------------------------------------------------
__global__ __launch_bounds__(256) void scores_kernel(
    const float* __restrict__ img,      // [B][D][P]
    const float* __restrict__ word,     // [C][D]
    const float* __restrict__ faw)      // [D]
{
    __shared__ float img_s[PT * SSTRIDE];
    const int b  = blockIdx.y;
    const int p0 = blockIdx.x * PT;
    const int tid = threadIdx.x;

    // Stage img tile: [PT pixels][D] -> smem, coalesced-ish gmem reads
    const float* imgb = img + (size_t)b * DD * PP;
    for (int i = tid; i < PT * DD; i += 256) {
        int p = i & (PT - 1), d = i >> 3;
        int gp = p0 + p;
        if (gp < PP) img_s[p * SSTRIDE + d] = imgb[d * PP + gp];
    }
    __syncthreads();

    const int lane = tid & 31, w = tid >> 5;
    const int p = p0 + w;
    if (p >= PP) return;

    // Load this thread's img slice + fc_a_w slice into registers,
    // and emit transposed img (coalesced float4 stores).
    float4 im[8], wv[8];
    const float4* faw4 = (const float4*)faw;
    float4* outT = (float4*)(g_imgT + ((size_t)b * PP + p) * DD);
    #pragma unroll
    for (int k = 0; k < 8; k++) {
        int d4 = lane + 32 * k;
        float4 v = *(const float4*)&img_s[w * SSTRIDE + 4 * d4];
        im[k] = v;
        outT[d4] = v;
        wv[k] = faw4[d4];
    }

    for (int c = 0; c < CC; c++) {
        const float4* wr = (const float4*)(word + c * DD);
        float a0 = 0.f, a1 = 0.f, a2 = 0.f, a3 = 0.f;
        #pragma unroll
        for (int k = 0; k < 8; k++) {
            float4 wd = wr[lane + 32 * k];
            a0 = fmaf(tanh_fast(im[k].x * wd.x), wv[k].x, a0);
            a1 = fmaf(tanh_fast(im[k].y * wd.y), wv[k].y, a1);
            a2 = fmaf(tanh_fast(im[k].z * wd.z), wv[k].z, a2);
            a3 = fmaf(tanh_fast(im[k].w * wd.w), wv[k].w, a3);
        }
        float acc = (a0 + a1) + (a2 + a3);
        #pragma unroll
        for (int o = 16; o; o >>= 1)
            acc += __shfl_xor_sync(0xFFFFFFFFu, acc, o);
        if (lane == 0)
            g_scores[((size_t)b * CC + c) * PP + p] = acc;
        // fc_a_b is a uniform shift over all spatial scores -> softmax-invariant
    }
}

// ---------------------------------------------------------------------------
// Phase 2: coef[b,p,c] = softmax over p of scores[b,c,p]. One warp per (b,c).
// grid 160, block 256 (8 warps).
// ---------------------------------------------------------------------------
__global__ __launch_bounds__(256) void softmax_kernel()
{
    const int gw   = blockIdx.x * 8 + (threadIdx.x >> 5);   // 0..1279
    const int lane = threadIdx.x & 31;
    const int b = gw / CC, c = gw % CC;

    const float* sc = g_scores + ((size_t)b * CC + c) * PP;
    float v[7];
    float mx = -1e30f;
    #pragma unroll
    for (int k = 0; k < 7; k++) {
        int p = lane + 32 * k;
        v[k] = (p < PP) ? sc[p] : -1e30f;
        mx = fmaxf(mx, v[k]);
    }
    #pragma unroll
    for (int o = 16; o; o >>= 1)
        mx = fmaxf(mx, __shfl_xor_sync(0xFFFFFFFFu, mx, o));

    float sum = 0.f;
    #pragma unroll
    for (int k = 0; k < 7; k++) {
        v[k] = __expf(v[k] - mx);      // invalid p -> exp(-inf) = 0
        sum += v[k];
    }
    #pragma unroll
    for (int o = 16; o; o >>= 1)
        sum += __shfl_xor_sync(0xFFFFFFFFu, sum, o);

    float inv = 1.0f / sum;
    #pragma unroll
    for (int k = 0; k < 7; k++) {
        int p = lane + 32 * k;
        if (p < PP)
            g_coef[((size_t)b * PP + p) * CC + c] = v[k] * inv;
    }
}

// ---------------------------------------------------------------------------
// Phase 3: out[b,c,d] = sum_p coef[b,p,c] * imgT[b,p,d]
// grid (8 d-tiles of 128, 16 b), block 256 (163KB dyn smem, 1 block/SM).
// Thread tile: 10 c x 4 d, packed fma.rn.f32x2 (pairs over c).
// ---------------------------------------------------------------------------
__global__ __launch_bounds__(256) void out_kernel(float* __restrict__ out)
{
    extern __shared__ float sm[];
    float* img_s  = sm;                 // [196][128]
    float* coef_s = sm + PP * 128;      // [196][80]

    const int b  = blockIdx.y;
    const int d0 = blockIdx.x * 128;
    const int tid = threadIdx.x;

    const float* imgT = g_imgT + (size_t)b * PP * DD;
    for (int i = tid; i < PP * 32; i += 256) {   // 196 * 128/4 float4s
        int pp = i >> 5, j = i & 31;
        ((float4*)img_s)[pp * 32 + j] = *(const float4*)(imgT + (size_t)pp * DD + d0 + 4 * j);
    }
    const float4* coefb = (const float4*)(g_coef + (size_t)b * PP * CC);
    for (int i = tid; i < PP * 20; i += 256)     // 196 * 80/4 float4s
        ((float4*)coef_s)[i] = coefb[i];
    __syncthreads();

    const int dg = tid & 31;            // lanes over d-quads (conflict-free LDS.128)
    const int cg = tid >> 5;            // warp = c-group (broadcast coef LDS.64)

    ull acc[5][4];
    #pragma unroll
    for (int j = 0; j < 5; j++)
        #pragma unroll
        for (int dd = 0; dd < 4; dd++) acc[j][dd] = 0ull;

    #pragma unroll 2
    for (int p = 0; p < PP; p++) {
        float4 iv = ((const float4*)img_s)[p * 32 + dg];
        ull ix = pack2(iv.x, iv.x);
        ull iy = pack2(iv.y, iv.y);
        ull iz = pack2(iv.z, iv.z);
        ull iw = pack2(iv.w, iv.w);
        const ull* cpr = (const ull*)(coef_s + p * CC + cg * 10);
        #pragma unroll
        for (int j = 0; j < 5; j++) {
            ull cc = cpr[j];            // (coef[c], coef[c+1])
            acc[j][0] = fma2(cc, ix, acc[j][0]);
            acc[j][1] = fma2(cc, iy, acc[j][1]);
            acc[j][2] = fma2(cc, iz, acc[j][2]);
            acc[j][3] = fma2(cc, iw, acc[j][3]);
        }
    }

    #pragma unroll
    for (int j = 0; j < 5; j++) {
        int c = cg * 10 + 2 * j;
        #pragma unroll
        for (int dd = 0; dd < 4; dd++) {
            float2 v = unpack2(acc[j][dd]);
            int d = d0 + 4 * dg + dd;
            out[((size_t)(b * CC + c))     * DD + d] = v.x;
            out[((size_t)(b * CC + c + 1)) * DD + d] = v.y;
        }
    }
}

// ---------------------------------------------------------------------------
extern "C" void kernel_launch(void* const* d_in, const int* in_sizes, int n_in,
                              void* d_out, int out_size)
{
    // inputs: [0]=batch_size (unused), [1]=img [16,1024,14,14],
    //         [2]=word [80,1024], [3]=fc_a_w [1024], [4]=fc_a_b (softmax-invariant)
    const float* img  = (const float*)d_in[1];
    const float* word = (const float*)d_in[2];
    const float* faw  = (const float*)d_in[3];
    float* out = (float*)d_out;

    const int smem3 = (PP * 128 + PP * CC) * (int)sizeof(float);  // 163,072 B
    cudaFuncSetAttribute(out_kernel, cudaFuncAttributeMaxDynamicSharedMemorySize, smem3);

    scores_kernel<<<dim3(25, BB), 256>>>(img, word, faw);
    softmax_kernel<<<160, 256>>>();
    out_kernel<<<dim3(8, BB), 256, smem3>>>(out);
}

// round 3
// speedup vs baseline: 1.1294x; 1.1294x over previous
#include <cuda_runtime.h>
#include <cuda_bf16.h>

// Problem constants (fixed by dataset): B=16, C=80, D=1024, S=14 (P=196)
#define BB 16
#define CC 80
#define DD 1024
#define PP 196
#define PT 8            // pixels per block in phase 1
#define SSTRIDE 1032    // padded smem stride (conflict-free both ways)

// Scratch (no allocation allowed -> device globals)
__device__ float g_imgT[BB * PP * DD];        // [b][p][d]  transposed img, 12.8MB
__device__ float g_scores[BB * CC * PP];      // [b][c][p]
__device__ float g_coef[BB * PP * CC];        // [b][p][c]

typedef unsigned long long ull;

__device__ __forceinline__ float tanh_fast(float x) {
    float y; asm("tanh.approx.f32 %0, %1;" : "=f"(y) : "f"(x)); return y;
}
__device__ __forceinline__ ull pack2(float a, float b) {
    ull r; asm("mov.b64 %0, {%1, %2};" : "=l"(r) : "f"(a), "f"(b)); return r;
}
__device__ __forceinline__ ull fma2(ull a, ull b, ull c) {
    ull d; asm("fma.rn.f32x2 %0, %1, %2, %3;" : "=l"(d) : "l"(a), "l"(b), "l"(c)); return d;
}
__device__ __forceinline__ float2 unpack2(ull a) {
    float lo, hi; asm("mov.b64 {%0, %1}, %2;" : "=f"(lo), "=f"(hi) : "l"(a));
    return make_float2(lo, hi);
}

// ---------------------------------------------------------------------------
// Phase 1: scores[b,c,p] = sum_d tanh(img[b,d,p]*word[c,d]) * w[d]
// Also writes imgT[b,p,d] (coalesced) for phase 3.
// grid (25, 16), block 256, 3 blocks/SM (single wave: 400 <= 444).
// Warp = pixel; img slice + fc_a_w slice register-resident; word row staged
// through smem with double-buffered cooperative prefetch (hides L2 latency).
// ---------------------------------------------------------------------------
__global__ __launch_bounds__(256, 3) void scores_kernel(
    const float* __restrict__ img,      // [B][D][P]
    const float* __restrict__ word,     // [C][D]
    const float* __restrict__ faw)      // [D]
{
    __shared__ float img_s[PT * SSTRIDE];       // 33 KB
    __shared__ float word_s[2][DD];             // 8 KB double buffer

    const int b  = blockIdx.y;
    const int p0 = blockIdx.x * PT;
    const int tid = threadIdx.x;

    // Stage img tile: [PT pixels][D] -> smem (tail pixels clamp, harmless dup)
    const float* imgb = img + (size_t)b * DD * PP;
    for (int i = tid; i < PT * DD; i += 256) {
        int p = i & (PT - 1), d = i >> 3;
        int gp = p0 + p; if (gp >= PP) gp = PP - 1;
        img_s[p * SSTRIDE + d] = imgb[d * PP + gp];
    }
    // Prefetch word row for class 0
    ((float4*)word_s[0])[tid] = ((const float4*)word)[tid];
    __syncthreads();

    const int lane = tid & 31, w = tid >> 5;
    const int p = p0 + w;
    const bool valid = (p < PP);

    // Register-cache this thread's img slice + fc_a_w slice,
    // and emit transposed img (coalesced float4 stores) for phase 3.
    float4 im[8], wv[8];
    const float4* faw4 = (const float4*)faw;
    {
        int pr = valid ? p : (PP - 1);
        float4* outT = (float4*)(g_imgT + ((size_t)b * PP + pr) * DD);
        #pragma unroll
        for (int k = 0; k < 8; k++) {
            int d4 = lane + 32 * k;
            float4 v = *(const float4*)&img_s[w * SSTRIDE + 4 * d4];
            im[k] = v;
            wv[k] = faw4[d4];
            if (valid) outT[d4] = v;
        }
    }

    const float4* wgp = (const float4*)word + tid;   // prefetch slot
    float* scb = g_scores + (size_t)b * CC * PP + p;

    #pragma unroll 2
    for (int c = 0; c < CC; c++) {
        // issue prefetch of next class's word row (L2 latency hidden by body)
        float4 pf;
        if (c + 1 < CC) pf = wgp[(c + 1) * (DD / 4)];

        const float4* ws = (const float4*)word_s[c & 1];
        float a0 = 0.f, a1 = 0.f, a2 = 0.f, a3 = 0.f;
        #pragma unroll
        for (int k = 0; k < 8; k++) {
            float4 wd = ws[lane + 32 * k];           // conflict-free LDS.128
            a0 = fmaf(tanh_fast(im[k].x * wd.x), wv[k].x, a0);
            a1 = fmaf(tanh_fast(im[k].y * wd.y), wv[k].y, a1);
            a2 = fmaf(tanh_fast(im[k].z * wd.z), wv[k].z, a2);
            a3 = fmaf(tanh_fast(im[k].w * wd.w), wv[k].w, a3);
        }
        float acc = (a0 + a1) + (a2 + a3);
        #pragma unroll
        for (int o = 16; o; o >>= 1)
            acc += __shfl_xor_sync(0xFFFFFFFFu, acc, o);
        if (lane == 0 && valid)
            scb[c * PP] = acc;
        // fc_a_b is a uniform shift over spatial scores -> softmax-invariant

        if (c + 1 < CC)
            ((float4*)word_s[(c + 1) & 1])[tid] = pf;
        __syncthreads();
    }
}

// ---------------------------------------------------------------------------
// Phase 2: coef[b,p,c] = softmax over p of scores[b,c,p]. One warp per (b,c).
// ---------------------------------------------------------------------------
__global__ __launch_bounds__(256) void softmax_kernel()
{
    const int gw   = blockIdx.x * 8 + (threadIdx.x >> 5);   // 0..1279
    const int lane = threadIdx.x & 31;
    const int b = gw / CC, c = gw % CC;

    const float* sc = g_scores + ((size_t)b * CC + c) * PP;
    float v[7];
    float mx = -1e30f;
    #pragma unroll
    for (int k = 0; k < 7; k++) {
        int p = lane + 32 * k;
        v[k] = (p < PP) ? sc[p] : -1e30f;
        mx = fmaxf(mx, v[k]);
    }
    #pragma unroll
    for (int o = 16; o; o >>= 1)
        mx = fmaxf(mx, __shfl_xor_sync(0xFFFFFFFFu, mx, o));

    float sum = 0.f;
    #pragma unroll
    for (int k = 0; k < 7; k++) {
        v[k] = __expf(v[k] - mx);      // invalid p -> exp(-inf) = 0
        sum += v[k];
    }
    #pragma unroll
    for (int o = 16; o; o >>= 1)
        sum += __shfl_xor_sync(0xFFFFFFFFu, sum, o);

    float inv = 1.0f / sum;
    #pragma unroll
    for (int k = 0; k < 7; k++) {
        int p = lane + 32 * k;
        if (p < PP)
            g_coef[((size_t)b * PP + p) * CC + c] = v[k] * inv;
    }
}

// ---------------------------------------------------------------------------
// Phase 3: out[b,c,d] = sum_p coef[b,p,c] * imgT[b,p,d]
// grid (8 d-tiles of 128, 16 b), block 256 (163KB dyn smem, 1 block/SM).
// Thread tile: 10 c x 4 d, packed fma.rn.f32x2 (pairs over c).
// ---------------------------------------------------------------------------
__global__ __launch_bounds__(256) void out_kernel(float* __restrict__ out)
{
    extern __shared__ float sm[];
    float* img_s  = sm;                 // [196][128]
    float* coef_s = sm + PP * 128;      // [196][80]

    const int b  = blockIdx.y;
    const int d0 = blockIdx.x * 128;
    const int tid = threadIdx.x;

    const float* imgT = g_imgT + (size_t)b * PP * DD;
    for (int i = tid; i < PP * 32; i += 256) {   // 196 * 128/4 float4s
        int pp = i >> 5, j = i & 31;
        ((float4*)img_s)[pp * 32 + j] = *(const float4*)(imgT + (size_t)pp * DD + d0 + 4 * j);
    }
    const float4* coefb = (const float4*)(g_coef + (size_t)b * PP * CC);
    for (int i = tid; i < PP * 20; i += 256)     // 196 * 80/4 float4s
        ((float4*)coef_s)[i] = coefb[i];
    __syncthreads();

    const int dg = tid & 31;            // lanes over d-quads (conflict-free LDS.128)
    const int cg = tid >> 5;            // warp = c-group (broadcast coef LDS.64)

    ull acc[5][4];
    #pragma unroll
    for (int j = 0; j < 5; j++)
        #pragma unroll
        for (int dd = 0; dd < 4; dd++) acc[j][dd] = 0ull;

    #pragma unroll 2
    for (int p = 0; p < PP; p++) {
        float4 iv = ((const float4*)img_s)[p * 32 + dg];
        ull ix = pack2(iv.x, iv.x);
        ull iy = pack2(iv.y, iv.y);
        ull iz = pack2(iv.z, iv.z);
        ull iw = pack2(iv.w, iv.w);
        const ull* cpr = (const ull*)(coef_s + p * CC + cg * 10);
        #pragma unroll
        for (int j = 0; j < 5; j++) {
            ull cc = cpr[j];            // (coef[c], coef[c+1])
            acc[j][0] = fma2(cc, ix, acc[j][0]);
            acc[j][1] = fma2(cc, iy, acc[j][1]);
            acc[j][2] = fma2(cc, iz, acc[j][2]);
            acc[j][3] = fma2(cc, iw, acc[j][3]);
        }
    }

    #pragma unroll
    for (int j = 0; j < 5; j++) {
        int c = cg * 10 + 2 * j;
        #pragma unroll
        for (int dd = 0; dd < 4; dd++) {
            float2 v = unpack2(acc[j][dd]);
            int d = d0 + 4 * dg + dd;
            out[((size_t)(b * CC + c))     * DD + d] = v.x;
            out[((size_t)(b * CC + c + 1)) * DD + d] = v.y;
        }
    }
}

// ---------------------------------------------------------------------------
extern "C" void kernel_launch(void* const* d_in, const int* in_sizes, int n_in,
                              void* d_out, int out_size)
{
    // inputs: [0]=batch_size (unused), [1]=img [16,1024,14,14],
    //         [2]=word [80,1024], [3]=fc_a_w [1024], [4]=fc_a_b (softmax-invariant)
    const float* img  = (const float*)d_in[1];
    const float* word = (const float*)d_in[2];
    const float* faw  = (const float*)d_in[3];
    float* out = (float*)d_out;

    const int smem3 = (PP * 128 + PP * CC) * (int)sizeof(float);  // 163,072 B
    cudaFuncSetAttribute(out_kernel, cudaFuncAttributeMaxDynamicSharedMemorySize, smem3);

    scores_kernel<<<dim3(25, BB), 256>>>(img, word, faw);
    softmax_kernel<<<160, 256>>>();
    out_kernel<<<dim3(8, BB), 256, smem3>>>(out);
}